// round 16
// baseline (speedup 1.0000x reference)
#include <cuda_runtime.h>
#include <cuda_bf16.h>

#define PP   4096
#define TT   128
#define AA   32
#define KSEL 409
#define INF_F 1e30f
#define TEMP_F 0.5f
#define FULLM 0xffffffffu
#define MARGIN 4                   // cp.async rows in flight
#define RINGR  (31 + MARGIN + 1)   // exact live span = 36 rows, 18 KB -> 12 blocks/SM

__device__ float    g_dists[PP];
__device__ int      g_eidx[KSEL];
__device__ float    g_ew[KSEL];
__device__ float    g_ssum;

// ---------------------------------------------------------------------------
// Kernel 1: DTW min-plus DP, skewed anti-diagonal. One 32-thread block per p.
// Lane l owns cols 4l..4l+3; at step s it computes row i = s - l.
// R15 profile: 22 KB ring -> 10 blocks/SM, DRAM 72%, occ 13.4% — right at the
// supply boundary. Shrinking MARGIN 12->4 (ring 36 rows, 18 KB) lifts
// residency to 12 blocks/SM; steady-state slack 4 steps x ~195 cyc > DRAM lat.
// Overwrite row s-32 vs oldest read s-31: exact-safe for any MARGIN.
// ---------------------------------------------------------------------------
__global__ void __launch_bounds__(32) dtw_kernel(const float* __restrict__ obs) {
    __shared__ float ring[RINGR * TT];   // 18432 B
    int lane = threadIdx.x;
    int p = blockIdx.x;

    const float* gp = obs + (size_t)p * (TT * TT) + lane * 4;
    unsigned sbase = (unsigned)__cvta_generic_to_shared(ring) + (lane << 4);

    // prologue: rows 0..MARGIN-1 in flight, one commit group per row
    #pragma unroll
    for (int r = 0; r < MARGIN; ++r) {
        unsigned dst = sbase + ((unsigned)r << 9);
        asm volatile("cp.async.cg.shared.global [%0], [%1], 16;\n"
                     :: "r"(dst), "l"(gp + r * TT));
        asm volatile("cp.async.commit_group;\n");
    }

    float d0 = INF_F, d1 = INF_F, d2 = INF_F, d3 = INF_F;
    float dl = (lane == 0) ? 0.0f : INF_F;   // D[i-1][4l-1] diagonal carry
    float expv = INF_F;                      // my d3 after previous step
    int   i = -lane;                         // my current row

    // incremental ring slots (equal i mod RINGR / r mod RINGR once valid)
    int rd = (RINGR - lane) % RINGR;         // slot of my row i (valid when i >= 0)
    int wr = MARGIN;                         // slot of row r = s + MARGIN

    for (int s = 0; s < TT + 31; ++s, ++i) {
        int r = s + MARGIN;
        if (r < TT) {
            unsigned dst = sbase + ((unsigned)wr << 9);
            asm volatile("cp.async.cg.shared.global [%0], [%1], 16;\n"
                         :: "r"(dst), "l"(gp + r * TT));
        }
        asm volatile("cp.async.commit_group;\n");
        asm volatile("cp.async.wait_group %0;\n" :: "n"(MARGIN));
        // after wait: rows 0..s resident; lane reads row i = s - lane <= s

        // neighbor's row-i last column D[i][4l-1] (produced at step s-1)
        float v = __shfl_up_sync(FULLM, expv, 1);
        if (lane == 0) v = INF_F;

        float4 c = *(const float4*)(ring + (rd << 7) + (lane << 2));
        if (i < 0) { c.x = INF_F; c.y = INF_F; c.z = INF_F; c.w = INF_F; }

        float t0 = fminf(d0, dl);
        float m1 = fminf(d1, d0);
        float m2 = fminf(d2, d1);
        float m3 = fminf(d3, d2);
        float x0 = fminf(t0, v)  + c.x;
        float x1 = fminf(m1, x0) + c.y;
        float x2 = fminf(m2, x1) + c.z;
        float x3 = fminf(m3, x2) + c.w;

        d0 = x0; d1 = x1; d2 = x2; d3 = x3;
        expv = x3;
        dl = v;

        rd = (rd + 1 == RINGR) ? 0 : rd + 1;
        wr = (wr + 1 == RINGR) ? 0 : wr + 1;
    }
    if (lane == 31) g_dists[p] = d3;   // D[127][127], computed at s = 158
}

// ---------------------------------------------------------------------------
// Kernel 2: single-block exact radix top-K + weights + elite compaction.
// ---------------------------------------------------------------------------
__global__ void __launch_bounds__(1024) select_kernel() {
    __shared__ unsigned hist[256];
    __shared__ unsigned wsum[32];
    __shared__ float    fred[32];
    __shared__ int      ired[32];
    __shared__ int      pofs[32];
    __shared__ float    s_min, s_Se;
    __shared__ unsigned s_prefix;
    __shared__ int      s_krem, s_cnt_lt;

    int tid = threadIdx.x, lane = tid & 31, wid = tid >> 5;

    float d[4]; unsigned u[4];
    float lmin = INF_F;
    #pragma unroll
    for (int e = 0; e < 4; ++e) {
        float x = g_dists[tid * 4 + e];
        d[e] = x;
        unsigned b = __float_as_uint(x);
        u[e] = b ^ ((b & 0x80000000u) ? 0xFFFFFFFFu : 0x80000000u);
        lmin = fminf(lmin, x);
    }
    if (tid == 0) { s_prefix = 0; s_krem = KSEL; s_cnt_lt = 0; }

    #pragma unroll
    for (int o = 16; o; o >>= 1) lmin = fminf(lmin, __shfl_xor_sync(FULLM, lmin, o));
    if (lane == 0) fred[wid] = lmin;
    __syncthreads();
    if (wid == 0) {
        float v = fred[lane];
        #pragma unroll
        for (int o = 16; o; o >>= 1) v = fminf(v, __shfl_xor_sync(FULLM, v, o));
        if (lane == 0) s_min = v;
    }
    __syncthreads();

    for (int shift = 24; shift >= 0; shift -= 8) {
        if (tid < 256) hist[tid] = 0;
        __syncthreads();
        unsigned pref  = s_prefix;
        int      krem  = s_krem;
        unsigned hmask = (shift == 24) ? 0u : (0xFFFFFFFFu << (shift + 8));
        #pragma unroll
        for (int e = 0; e < 4; ++e)
            if ((u[e] & hmask) == pref) atomicAdd(&hist[(u[e] >> shift) & 255], 1u);
        __syncthreads();
        unsigned v = 0, inc = 0;
        if (tid < 256) {
            v = hist[tid];
            inc = v;
            #pragma unroll
            for (int o = 1; o < 32; o <<= 1) {
                unsigned x = __shfl_up_sync(FULLM, inc, o);
                if (lane >= o) inc += x;
            }
            if (lane == 31) wsum[wid] = inc;
        }
        __syncthreads();
        if (tid < 256) {
            unsigned off = 0;
            #pragma unroll
            for (int k = 0; k < 8; ++k) off += (k < wid) ? wsum[k] : 0u;
            unsigned cum  = off + inc;
            unsigned prev = cum - v;
            if (prev < (unsigned)krem && (unsigned)krem <= cum) {
                s_prefix = pref | ((unsigned)tid << shift);
                s_krem   = krem - (int)prev;
            }
        }
        __syncthreads();
    }
    unsigned tau = s_prefix;

    int clt = 0, tc = 0;
    #pragma unroll
    for (int e = 0; e < 4; ++e) { clt += (u[e] < tau); tc += (u[e] == tau); }
    atomicAdd(&s_cnt_lt, clt);

    int incl = tc;
    #pragma unroll
    for (int o = 1; o < 32; o <<= 1) { int v = __shfl_up_sync(FULLM, incl, o); if (lane >= o) incl += v; }
    if (lane == 31) ired[wid] = incl;
    __syncthreads();
    if (wid == 0) {
        int v = ired[lane], s = v;
        #pragma unroll
        for (int o = 1; o < 32; o <<= 1) { int w2 = __shfl_up_sync(FULLM, s, o); if (lane >= o) s += w2; }
        ired[lane] = s - v;
    }
    __syncthreads();

    int trank = ired[wid] + (incl - tc);
    int need  = KSEL - s_cnt_lt;
    float mind = s_min;

    bool  sel[4]; float ws[4]; float esum = 0.f; int nsel = 0;
    #pragma unroll
    for (int e = 0; e < 4; ++e) {
        bool s = (u[e] < tau);
        if (u[e] == tau) { s = (trank < need); trank++; }
        sel[e] = s;
        float w = s ? expf(TEMP_F * (mind - d[e])) : 0.f;
        ws[e] = w; esum += w; nsel += s;
    }

    float se = esum;
    #pragma unroll
    for (int o = 16; o; o >>= 1) se += __shfl_xor_sync(FULLM, se, o);
    if (lane == 0) fred[wid] = se;
    __syncthreads();
    if (wid == 0) {
        float v = fred[lane];
        #pragma unroll
        for (int o = 16; o; o >>= 1) v += __shfl_xor_sync(FULLM, v, o);
        if (lane == 0) s_Se = v;
    }
    __syncthreads();
    float Se = s_Se;

    int pincl = nsel;
    #pragma unroll
    for (int o = 1; o < 32; o <<= 1) { int v = __shfl_up_sync(FULLM, pincl, o); if (lane >= o) pincl += v; }
    if (lane == 31) pofs[wid] = pincl;
    __syncthreads();
    if (wid == 0) {
        int v = pofs[lane], s = v;
        #pragma unroll
        for (int o = 1; o < 32; o <<= 1) { int w2 = __shfl_up_sync(FULLM, s, o); if (lane >= o) s += w2; }
        pofs[lane] = s - v;
    }
    __syncthreads();
    int pos = pofs[wid] + (pincl - nsel);

    float ssl = 0.f;
    #pragma unroll
    for (int e = 0; e < 4; ++e) {
        if (sel[e]) {
            float sc = ws[e] / Se;
            g_eidx[pos] = tid * 4 + e;
            g_ew[pos]   = sc;
            pos++;
            ssl += sc;
        }
    }

    #pragma unroll
    for (int o = 16; o; o >>= 1) ssl += __shfl_xor_sync(FULLM, ssl, o);
    if (lane == 0) fred[wid] = ssl;
    __syncthreads();
    if (wid == 0) {
        float v = fred[lane];
        #pragma unroll
        for (int o = 16; o; o >>= 1) v += __shfl_xor_sync(FULLM, v, o);
        if (lane == 0) g_ssum = v;
    }
}

// ---------------------------------------------------------------------------
// Kernel 3: weighted mean/std over the compacted elite list. One block per t.
// ---------------------------------------------------------------------------
__global__ void __launch_bounds__(512) reduce_kernel(const float* __restrict__ means,
                                                     const float* __restrict__ stds,
                                                     const float* __restrict__ noise,
                                                     float* __restrict__ out) {
    __shared__ float s1s[16][AA];
    __shared__ float s2s[16][AA];
    int t  = blockIdx.x;
    int a  = threadIdx.x & 31;
    int wg = threadIdx.x >> 5;

    float mn = means[t * AA + a];
    float sd = stds[t * AA + a];
    const float* np = noise + (size_t)t * PP * AA;

    float s1 = 0.f, s2 = 0.f;
    #pragma unroll 4
    for (int k = wg; k < KSEL; k += 16) {
        int   p = g_eidx[k];
        float w = g_ew[k];
        float x = fmaf(sd, __ldg(&np[(size_t)p * AA + a]), mn);
        x = fminf(fmaxf(x, -1.f), 1.f);
        s1 = fmaf(w, x, s1);
        s2 = fmaf(w * x, x, s2);
    }
    s1s[wg][a] = s1; s2s[wg][a] = s2;
    __syncthreads();

    if (wg == 0) {
        float S1 = 0.f, S2 = 0.f;
        #pragma unroll
        for (int k = 0; k < 16; ++k) { S1 += s1s[k][a]; S2 += s2s[k][a]; }
        float ssum  = g_ssum;
        float denom = ssum + 1e-9f;
        float m   = S1 / denom;
        float var = (S2 - 2.f * m * S1 + m * m * ssum) / denom;
        var = fmaxf(var, 0.f);
        float st = sqrtf(var);
        st = fminf(fmaxf(st, 0.05f), 1.0f);
        out[t * AA + a]           = 0.1f * mn + 0.9f * m;
        out[TT * AA + t * AA + a] = st;
    }
}

extern "C" void kernel_launch(void* const* d_in, const int* in_sizes, int n_in,
                              void* d_out, int out_size) {
    const float* obs   = (const float*)d_in[0];  // [P, T, T]
    const float* means = (const float*)d_in[1];  // [T, 1, A]
    const float* stds  = (const float*)d_in[2];  // [T, 1, A]
    const float* noise = (const float*)d_in[3];  // [T, P, A]
    float* out = (float*)d_out;                  // [2, T, 1, A]

    dtw_kernel<<<PP, 32>>>(obs);                 // one 32-thread block per p
    select_kernel<<<1, 1024>>>();
    reduce_kernel<<<TT, 512>>>(means, stds, noise, out);
}